// round 1
// baseline (speedup 1.0000x reference)
#include <cuda_runtime.h>
#include <cuda_bf16.h>
#include <cstdint>

// Problem sizes (fixed by the reference)
#define NS0 300000
#define ND0 50000
#define NE0 800000
#define NS1 50000
#define ND1 8192
#define NE1 131072
#define INF 256   // in_f
#define HIDF 128  // hid_f
#define OUTF 128  // out_f

// ---------------- static device scratch (no allocations allowed) ----------------
__device__ int   g_deg_out0[NS0];
__device__ int   g_deg_in0[ND0];
__device__ int   g_rowptr0[ND0 + 1];
__device__ int   g_fill0[ND0];
__device__ int   g_csr_src0[NE0];
__device__ float g_csr_w0[NE0];
__device__ float g_agg0[(size_t)ND0 * INF];    // 51.2 MB
__device__ float g_h1[(size_t)ND0 * HIDF];     // 25.6 MB

__device__ int   g_deg_out1[NS1];
__device__ int   g_deg_in1[ND1];
__device__ int   g_rowptr1[ND1 + 1];
__device__ int   g_fill1[ND1];
__device__ int   g_csr_src1[NE1];
__device__ float g_csr_w1[NE1];
__device__ float g_agg1[(size_t)ND1 * HIDF];   // 4.2 MB

// ---------------- kernels ----------------

__global__ void k_zero() {
    int i = blockIdx.x * blockDim.x + threadIdx.x;
    int stride = gridDim.x * blockDim.x;
    for (int j = i; j < NS0; j += stride) g_deg_out0[j] = 0;
    for (int j = i; j < ND0; j += stride) {
        g_deg_in0[j] = 0;
        g_fill0[j] = 0;
        g_deg_out1[j] = 0;   // NS1 == ND0
    }
    for (int j = i; j < ND1; j += stride) {
        g_deg_in1[j] = 0;
        g_fill1[j] = 0;
    }
}

__global__ void k_degree(const int* __restrict__ src0, const int* __restrict__ dst0,
                         const int* __restrict__ src1, const int* __restrict__ dst1) {
    int i = blockIdx.x * blockDim.x + threadIdx.x;
    int stride = gridDim.x * blockDim.x;
    for (int e = i; e < NE0; e += stride) {
        atomicAdd(&g_deg_out0[src0[e]], 1);
        atomicAdd(&g_deg_in0[dst0[e]], 1);
        if (e < NE1) {
            atomicAdd(&g_deg_out1[src1[e]], 1);
            atomicAdd(&g_deg_in1[dst1[e]], 1);
        }
    }
}

// Exclusive scan of `n` ints by a single 1024-thread block.
__device__ __forceinline__ void scan_body(const int* __restrict__ deg,
                                          int* __restrict__ rowptr, int n) {
    __shared__ int partial[1024];
    const int t = threadIdx.x;
    const int C = (n + 1023) / 1024;
    const int start = t * C;
    const int end = min(start + C, n);
    int s = 0;
    for (int i = start; i < end; i++) s += deg[i];
    partial[t] = s;
    __syncthreads();
    // Hillis-Steele inclusive scan over 1024
    for (int off = 1; off < 1024; off <<= 1) {
        int v = partial[t];
        int add = (t >= off) ? partial[t - off] : 0;
        __syncthreads();
        partial[t] = v + add;
        __syncthreads();
    }
    int run = (t == 0) ? 0 : partial[t - 1];
    for (int i = start; i < end; i++) {
        rowptr[i] = run;
        run += deg[i];
    }
    if (t == 0) rowptr[n] = partial[1023];
}

__global__ void k_scan0() { scan_body(g_deg_in0, g_rowptr0, ND0); }
__global__ void k_scan1() { scan_body(g_deg_in1, g_rowptr1, ND1); }

__global__ void k_fill(const int* __restrict__ src0, const int* __restrict__ dst0,
                       const float* __restrict__ ew0,
                       const int* __restrict__ src1, const int* __restrict__ dst1,
                       const float* __restrict__ ew1) {
    int i = blockIdx.x * blockDim.x + threadIdx.x;
    int stride = gridDim.x * blockDim.x;
    for (int e = i; e < NE0; e += stride) {
        int s = src0[e];
        int d = dst0[e];
        int pos = g_rowptr0[d] + atomicAdd(&g_fill0[d], 1);
        g_csr_src0[pos] = s;
        g_csr_w0[pos] = ew0[e] * rsqrtf(fmaxf((float)g_deg_out0[s], 1.0f));
        if (e < NE1) {
            int s1 = src1[e];
            int d1 = dst1[e];
            int pos1 = g_rowptr1[d1] + atomicAdd(&g_fill1[d1], 1);
            g_csr_src1[pos1] = s1;
            g_csr_w1[pos1] = ew1[e] * rsqrtf(fmaxf((float)g_deg_out1[s1], 1.0f));
        }
    }
}

// One block per destination row; blockDim == D. Accumulates
// sum_e w_e * feat[src_e][tid], scales by indeg^-0.5, writes out.
template <int D>
__device__ __forceinline__ void agg_body(const int* __restrict__ rowptr,
                                         const int* __restrict__ csrsrc,
                                         const float* __restrict__ csrw,
                                         const float* __restrict__ feat,
                                         const int* __restrict__ indeg,
                                         float* __restrict__ outbuf) {
    const int row = blockIdx.x;
    const int tid = threadIdx.x;
    const int beg = rowptr[row];
    const int end = rowptr[row + 1];
    float acc = 0.0f;
    int j = beg;
    for (; j + 4 <= end; j += 4) {
        int s0 = csrsrc[j + 0], s1 = csrsrc[j + 1], s2 = csrsrc[j + 2], s3 = csrsrc[j + 3];
        float w0 = csrw[j + 0], w1 = csrw[j + 1], w2 = csrw[j + 2], w3 = csrw[j + 3];
        float f0 = feat[(size_t)s0 * D + tid];
        float f1 = feat[(size_t)s1 * D + tid];
        float f2 = feat[(size_t)s2 * D + tid];
        float f3 = feat[(size_t)s3 * D + tid];
        acc += w0 * f0;
        acc += w1 * f1;
        acc += w2 * f2;
        acc += w3 * f3;
    }
    for (; j < end; j++) acc += csrw[j] * feat[(size_t)csrsrc[j] * D + tid];
    float sc = rsqrtf(fmaxf((float)indeg[row], 1.0f));
    outbuf[(size_t)row * D + tid] = acc * sc;
}

__global__ void __launch_bounds__(256) k_agg0(const float* __restrict__ x) {
    agg_body<INF>(g_rowptr0, g_csr_src0, g_csr_w0, x, g_deg_in0, g_agg0);
}
__global__ void __launch_bounds__(128) k_agg1() {
    agg_body<HIDF>(g_rowptr1, g_csr_src1, g_csr_w1, g_h1, g_deg_in1, g_agg1);
}

// out[nrows,128] = relu(A[nrows,K] @ W[K,128] + bias). blockDim = 256.
// Tile: 32 rows x 128 cols per block, 4x4 register blocking per thread.
template <int K>
__device__ __forceinline__ void gemm_body(const float* __restrict__ A, int nrows,
                                          const float* __restrict__ W,
                                          const float* __restrict__ bias,
                                          float* __restrict__ out) {
    __shared__ float Wsh[64][128];
    __shared__ float Ash[32][64];
    __shared__ float bsh[128];
    const int tid = threadIdx.x;
    if (tid < 128) bsh[tid] = bias[tid];
    const int colg = tid & 31;  // cols colg*4 .. colg*4+3
    const int rowg = tid >> 5;  // rows rowg*4 .. rowg*4+3 (within 32-row tile)
    const int base = blockIdx.x * 32;
    if (base >= nrows) return;

    float acc[4][4];
#pragma unroll
    for (int r = 0; r < 4; r++)
#pragma unroll
        for (int c = 0; c < 4; c++) acc[r][c] = 0.0f;

    for (int kc = 0; kc < K; kc += 64) {
        __syncthreads();
#pragma unroll
        for (int i = tid; i < 32 * 64; i += 256) {
            int r = i >> 6, k = i & 63;
            int row = base + r;
            Ash[r][k] = (row < nrows) ? A[(size_t)row * K + kc + k] : 0.0f;
        }
#pragma unroll
        for (int i = tid; i < 64 * 128; i += 256) {
            int k = i >> 7, c = i & 127;
            Wsh[k][c] = W[(size_t)(kc + k) * 128 + c];
        }
        __syncthreads();
#pragma unroll
        for (int k = 0; k < 64; k++) {
            float4 w = *(const float4*)&Wsh[k][colg * 4];
            float a0 = Ash[rowg * 4 + 0][k];
            float a1 = Ash[rowg * 4 + 1][k];
            float a2 = Ash[rowg * 4 + 2][k];
            float a3 = Ash[rowg * 4 + 3][k];
            acc[0][0] += a0 * w.x; acc[0][1] += a0 * w.y; acc[0][2] += a0 * w.z; acc[0][3] += a0 * w.w;
            acc[1][0] += a1 * w.x; acc[1][1] += a1 * w.y; acc[1][2] += a1 * w.z; acc[1][3] += a1 * w.w;
            acc[2][0] += a2 * w.x; acc[2][1] += a2 * w.y; acc[2][2] += a2 * w.z; acc[2][3] += a2 * w.w;
            acc[3][0] += a3 * w.x; acc[3][1] += a3 * w.y; acc[3][2] += a3 * w.z; acc[3][3] += a3 * w.w;
        }
    }

#pragma unroll
    for (int r = 0; r < 4; r++) {
        int row = base + rowg * 4 + r;
        if (row < nrows) {
            int c0 = colg * 4;
            float4 v;
            v.x = fmaxf(acc[r][0] + bsh[c0 + 0], 0.0f);
            v.y = fmaxf(acc[r][1] + bsh[c0 + 1], 0.0f);
            v.z = fmaxf(acc[r][2] + bsh[c0 + 2], 0.0f);
            v.w = fmaxf(acc[r][3] + bsh[c0 + 3], 0.0f);
            *(float4*)&out[(size_t)row * 128 + c0] = v;
        }
    }
}

__global__ void __launch_bounds__(256) k_gemm1(const float* __restrict__ W,
                                               const float* __restrict__ b) {
    gemm_body<INF>(g_agg0, ND0, W, b, g_h1);
}
__global__ void __launch_bounds__(256) k_gemm2(const float* __restrict__ W,
                                               const float* __restrict__ b,
                                               float* __restrict__ out) {
    gemm_body<HIDF>(g_agg1, ND1, W, b, out);
}

// ---------------- launch ----------------
extern "C" void kernel_launch(void* const* d_in, const int* in_sizes, int n_in,
                              void* d_out, int out_size) {
    const float* x    = (const float*)d_in[0];
    const int*   src0 = (const int*)d_in[1];
    const int*   dst0 = (const int*)d_in[2];
    const float* ew0  = (const float*)d_in[3];
    const int*   src1 = (const int*)d_in[4];
    const int*   dst1 = (const int*)d_in[5];
    const float* ew1  = (const float*)d_in[6];
    const float* W1   = (const float*)d_in[7];
    const float* b1   = (const float*)d_in[8];
    const float* W2   = (const float*)d_in[9];
    const float* b2   = (const float*)d_in[10];
    float* out = (float*)d_out;

    k_zero<<<512, 256>>>();
    k_degree<<<3125, 256>>>(src0, dst0, src1, dst1);
    k_scan0<<<1, 1024>>>();
    k_scan1<<<1, 1024>>>();
    k_fill<<<3125, 256>>>(src0, dst0, ew0, src1, dst1, ew1);
    k_agg0<<<ND0, 256>>>(x);
    k_gemm1<<<(ND0 + 31) / 32, 256>>>(W1, b1);
    k_agg1<<<ND1, 128>>>();
    k_gemm2<<<(ND1 + 31) / 32, 256>>>(W2, b2, out);
}

// round 2
// speedup vs baseline: 1.2580x; 1.2580x over previous
#include <cuda_runtime.h>
#include <cuda_bf16.h>
#include <cstdint>

// Problem sizes (fixed by the reference)
#define NS0 300000
#define ND0 50000
#define NE0 800000
#define NS1 50000
#define ND1 8192
#define NE1 131072
#define INF 256   // in_f
#define HIDF 128  // hid_f
#define OUTF 128  // out_f

// ---------------- static device scratch (no allocations allowed) ----------------
__device__ int   g_deg_out0[NS0];
__device__ int   g_deg_in0[ND0];
__device__ int   g_rowptr0[ND0 + 1];
__device__ int   g_fill0[ND0];
__device__ int   g_csr_src0[NE0];
__device__ float g_csr_w0[NE0];
__device__ float g_agg0[(size_t)ND0 * INF];    // 51.2 MB
__device__ float g_h1[(size_t)ND0 * HIDF];     // 25.6 MB

__device__ int   g_deg_out1[NS1];
__device__ int   g_deg_in1[ND1];
__device__ int   g_rowptr1[ND1 + 1];
__device__ int   g_fill1[ND1];
__device__ int   g_csr_src1[NE1];
__device__ float g_csr_w1[NE1];
__device__ float g_agg1[(size_t)ND1 * HIDF];   // 4.2 MB

// ---------------- helpers ----------------
__device__ __forceinline__ uint32_t f2tf32(float f) {
    uint32_t r;
    asm("cvt.rna.tf32.f32 %0, %1;" : "=r"(r) : "f"(f));
    return r;
}

__device__ __forceinline__ void mma_tf32(float d[4], const uint32_t a[4],
                                         const uint32_t b0, const uint32_t b1,
                                         const float c[4]) {
    asm volatile(
        "mma.sync.aligned.m16n8k8.row.col.f32.tf32.tf32.f32 "
        "{%0,%1,%2,%3}, {%4,%5,%6,%7}, {%8,%9}, {%10,%11,%12,%13};\n"
        : "=f"(d[0]), "=f"(d[1]), "=f"(d[2]), "=f"(d[3])
        : "r"(a[0]), "r"(a[1]), "r"(a[2]), "r"(a[3]),
          "r"(b0), "r"(b1),
          "f"(c[0]), "f"(c[1]), "f"(c[2]), "f"(c[3]));
}

// ---------------- kernels ----------------

__global__ void k_zero() {
    int i = blockIdx.x * blockDim.x + threadIdx.x;
    int stride = gridDim.x * blockDim.x;
    for (int j = i; j < NS0; j += stride) g_deg_out0[j] = 0;
    for (int j = i; j < ND0; j += stride) {
        g_deg_in0[j] = 0;
        g_fill0[j] = 0;
        g_deg_out1[j] = 0;   // NS1 == ND0
    }
    for (int j = i; j < ND1; j += stride) {
        g_deg_in1[j] = 0;
        g_fill1[j] = 0;
    }
}

__global__ void k_degree(const int* __restrict__ src0, const int* __restrict__ dst0,
                         const int* __restrict__ src1, const int* __restrict__ dst1) {
    int i = blockIdx.x * blockDim.x + threadIdx.x;
    int stride = gridDim.x * blockDim.x;
    for (int e = i; e < NE0; e += stride) {
        atomicAdd(&g_deg_out0[src0[e]], 1);
        atomicAdd(&g_deg_in0[dst0[e]], 1);
        if (e < NE1) {
            atomicAdd(&g_deg_out1[src1[e]], 1);
            atomicAdd(&g_deg_in1[dst1[e]], 1);
        }
    }
}

// Exclusive scan of `n` ints by a single 1024-thread block.
__device__ __forceinline__ void scan_body(const int* __restrict__ deg,
                                          int* __restrict__ rowptr, int n) {
    __shared__ int partial[1024];
    const int t = threadIdx.x;
    const int C = (n + 1023) / 1024;
    const int start = t * C;
    const int end = min(start + C, n);
    int s = 0;
    for (int i = start; i < end; i++) s += deg[i];
    partial[t] = s;
    __syncthreads();
    for (int off = 1; off < 1024; off <<= 1) {
        int v = partial[t];
        int add = (t >= off) ? partial[t - off] : 0;
        __syncthreads();
        partial[t] = v + add;
        __syncthreads();
    }
    int run = (t == 0) ? 0 : partial[t - 1];
    for (int i = start; i < end; i++) {
        rowptr[i] = run;
        run += deg[i];
    }
    if (t == 0) rowptr[n] = partial[1023];
}

// Merged: block 0 scans layer-0 degrees, block 1 scans layer-1 degrees.
__global__ void k_scan_both() {
    if (blockIdx.x == 0) scan_body(g_deg_in0, g_rowptr0, ND0);
    else                 scan_body(g_deg_in1, g_rowptr1, ND1);
}

__global__ void k_fill(const int* __restrict__ src0, const int* __restrict__ dst0,
                       const float* __restrict__ ew0,
                       const int* __restrict__ src1, const int* __restrict__ dst1,
                       const float* __restrict__ ew1) {
    int i = blockIdx.x * blockDim.x + threadIdx.x;
    int stride = gridDim.x * blockDim.x;
    for (int e = i; e < NE0; e += stride) {
        int s = src0[e];
        int d = dst0[e];
        int pos = g_rowptr0[d] + atomicAdd(&g_fill0[d], 1);
        g_csr_src0[pos] = s;
        g_csr_w0[pos] = ew0[e] * rsqrtf(fmaxf((float)g_deg_out0[s], 1.0f));
        if (e < NE1) {
            int s1 = src1[e];
            int d1 = dst1[e];
            int pos1 = g_rowptr1[d1] + atomicAdd(&g_fill1[d1], 1);
            g_csr_src1[pos1] = s1;
            g_csr_w1[pos1] = ew1[e] * rsqrtf(fmaxf((float)g_deg_out1[s1], 1.0f));
        }
    }
}

// One block per destination row; blockDim == D. Accumulates
// sum_e w_e * feat[src_e][tid], scales by indeg^-0.5, writes out.
template <int D>
__device__ __forceinline__ void agg_body(const int* __restrict__ rowptr,
                                         const int* __restrict__ csrsrc,
                                         const float* __restrict__ csrw,
                                         const float* __restrict__ feat,
                                         const int* __restrict__ indeg,
                                         float* __restrict__ outbuf) {
    const int row = blockIdx.x;
    const int tid = threadIdx.x;
    const int beg = rowptr[row];
    const int end = rowptr[row + 1];
    float acc = 0.0f;
    int j = beg;
    // 8-wide unroll for deep MLP on the dominant gather stream
    for (; j + 8 <= end; j += 8) {
        int   s[8];
        float w[8];
#pragma unroll
        for (int u = 0; u < 8; u++) {
            s[u] = __ldg(&csrsrc[j + u]);
            w[u] = __ldg(&csrw[j + u]);
        }
        float f[8];
#pragma unroll
        for (int u = 0; u < 8; u++) f[u] = __ldg(&feat[(size_t)s[u] * D + tid]);
#pragma unroll
        for (int u = 0; u < 8; u++) acc += w[u] * f[u];
    }
    for (; j < end; j++) acc += __ldg(&csrw[j]) * __ldg(&feat[(size_t)csrsrc[j] * D + tid]);
    float sc = rsqrtf(fmaxf((float)indeg[row], 1.0f));
    outbuf[(size_t)row * D + tid] = acc * sc;
}

__global__ void __launch_bounds__(256) k_agg0(const float* __restrict__ x) {
    agg_body<INF>(g_rowptr0, g_csr_src0, g_csr_w0, x, g_deg_in0, g_agg0);
}
__global__ void __launch_bounds__(128) k_agg1() {
    agg_body<HIDF>(g_rowptr1, g_csr_src1, g_csr_w1, g_h1, g_deg_in1, g_agg1);
}

// ---------------- TF32 tensor-core GEMM ----------------
// out[nrows,128] = relu(A[nrows,K] @ W[K,128] + bias)
// Block: 128 threads = 4 warps (2 along M x 2 along N).
// Block tile: 64 rows x 128 cols, K-chunk 32.
// Warp tile: 32 rows x 64 cols = 2 m-tiles x 8 n-tiles of m16n8k8.
// Smem strides chosen for conflict-free fragment loads:
//   Ash stride 36 -> bank = (4r + c) % 32, all 32 lanes distinct.
//   Wsh stride 136 -> bank = (8k + n) % 32, all 32 lanes distinct.
template <int K>
__global__ void __launch_bounds__(128) k_gemm_tf32(const float* __restrict__ A, int nrows,
                                                   const float* __restrict__ W,
                                                   const float* __restrict__ bias,
                                                   float* __restrict__ out) {
    __shared__ uint32_t Ash[64 * 36];
    __shared__ uint32_t Wsh[32 * 136];

    const int tid = threadIdx.x;
    const int lane = tid & 31;
    const int warp = tid >> 5;
    const int warpM = warp & 1;   // 0..1
    const int warpN = warp >> 1;  // 0..1
    const int base = blockIdx.x * 64;

    float acc[2][8][4];
#pragma unroll
    for (int mt = 0; mt < 2; mt++)
#pragma unroll
        for (int nt = 0; nt < 8; nt++)
#pragma unroll
            for (int i = 0; i < 4; i++) acc[mt][nt][i] = 0.0f;

    for (int kc = 0; kc < K; kc += 32) {
        __syncthreads();
        // Load A tile 64x32 (convert to tf32 on store)
#pragma unroll
        for (int it = 0; it < 4; it++) {
            int r = (tid >> 3) + it * 16;
            int c = (tid & 7) * 4;
            int row = base + r;
            float4 v;
            if (row < nrows) v = *(const float4*)&A[(size_t)row * K + kc + c];
            else             v = make_float4(0.f, 0.f, 0.f, 0.f);
            uint32_t* dst = &Ash[r * 36 + c];
            dst[0] = f2tf32(v.x); dst[1] = f2tf32(v.y);
            dst[2] = f2tf32(v.z); dst[3] = f2tf32(v.w);
        }
        // Load W tile 32x128
#pragma unroll
        for (int it = 0; it < 8; it++) {
            int kk = (tid >> 5) + it * 4;
            int n = (tid & 31) * 4;
            float4 v = *(const float4*)&W[(size_t)(kc + kk) * 128 + n];
            uint32_t* dst = &Wsh[kk * 136 + n];
            dst[0] = f2tf32(v.x); dst[1] = f2tf32(v.y);
            dst[2] = f2tf32(v.z); dst[3] = f2tf32(v.w);
        }
        __syncthreads();

#pragma unroll
        for (int k8 = 0; k8 < 4; k8++) {
            const int kb = k8 * 8;
            // A fragments for both m-tiles
            uint32_t afr[2][4];
            const int rA = warpM * 32 + (lane >> 2);
            const int cA = kb + (lane & 3);
#pragma unroll
            for (int mt = 0; mt < 2; mt++) {
                const int r0 = rA + mt * 16;
                afr[mt][0] = Ash[r0 * 36 + cA];
                afr[mt][1] = Ash[(r0 + 8) * 36 + cA];
                afr[mt][2] = Ash[r0 * 36 + cA + 4];
                afr[mt][3] = Ash[(r0 + 8) * 36 + cA + 4];
            }
            const int kkB = kb + (lane & 3);
#pragma unroll
            for (int nt = 0; nt < 8; nt++) {
                const int n = warpN * 64 + nt * 8 + (lane >> 2);
                uint32_t b0 = Wsh[kkB * 136 + n];
                uint32_t b1 = Wsh[(kkB + 4) * 136 + n];
                mma_tf32(acc[0][nt], afr[0], b0, b1, acc[0][nt]);
                mma_tf32(acc[1][nt], afr[1], b0, b1, acc[1][nt]);
            }
        }
    }

    // Epilogue: bias + relu
#pragma unroll
    for (int mt = 0; mt < 2; mt++) {
#pragma unroll
        for (int nt = 0; nt < 8; nt++) {
            int col = warpN * 64 + nt * 8 + (lane & 3) * 2;
            float bb0 = __ldg(&bias[col]);
            float bb1 = __ldg(&bias[col + 1]);
            int r0 = base + warpM * 32 + mt * 16 + (lane >> 2);
            if (r0 < nrows) {
                float2 v;
                v.x = fmaxf(acc[mt][nt][0] + bb0, 0.0f);
                v.y = fmaxf(acc[mt][nt][1] + bb1, 0.0f);
                *(float2*)&out[(size_t)r0 * 128 + col] = v;
            }
            int r1 = r0 + 8;
            if (r1 < nrows) {
                float2 v;
                v.x = fmaxf(acc[mt][nt][2] + bb0, 0.0f);
                v.y = fmaxf(acc[mt][nt][3] + bb1, 0.0f);
                *(float2*)&out[(size_t)r1 * 128 + col] = v;
            }
        }
    }
}

// ---------------- launch ----------------
extern "C" void kernel_launch(void* const* d_in, const int* in_sizes, int n_in,
                              void* d_out, int out_size) {
    const float* x    = (const float*)d_in[0];
    const int*   src0 = (const int*)d_in[1];
    const int*   dst0 = (const int*)d_in[2];
    const float* ew0  = (const float*)d_in[3];
    const int*   src1 = (const int*)d_in[4];
    const int*   dst1 = (const int*)d_in[5];
    const float* ew1  = (const float*)d_in[6];
    const float* W1   = (const float*)d_in[7];
    const float* b1   = (const float*)d_in[8];
    const float* W2   = (const float*)d_in[9];
    const float* b2   = (const float*)d_in[10];
    float* out = (float*)d_out;

    float* agg0 = nullptr; float* h1 = nullptr; float* agg1 = nullptr;
    cudaGetSymbolAddress((void**)&agg0, g_agg0);
    cudaGetSymbolAddress((void**)&h1,   g_h1);
    cudaGetSymbolAddress((void**)&agg1, g_agg1);

    k_zero<<<512, 256>>>();
    k_degree<<<3125, 256>>>(src0, dst0, src1, dst1);
    k_scan_both<<<2, 1024>>>();
    k_fill<<<3125, 256>>>(src0, dst0, ew0, src1, dst1, ew1);
    k_agg0<<<ND0, 256>>>(x);
    k_gemm_tf32<INF><<<(ND0 + 63) / 64, 128>>>(agg0, ND0, W1, b1, h1);
    k_agg1<<<ND1, 128>>>();
    k_gemm_tf32<HIDF><<<(ND1 + 63) / 64, 128>>>(agg1, ND1, W2, b2, out);
}

// round 3
// speedup vs baseline: 1.4141x; 1.1241x over previous
#include <cuda_runtime.h>
#include <cuda_bf16.h>
#include <cstdint>

#define NS0 300000
#define ND0 50000
#define NE0 800000
#define NS1 50000
#define ND1 8192
#define NE1 131072
#define INF 256
#define HIDF 128
#define OUTF 128

// ---------------- static device scratch ----------------
__device__ int   g_deg_out0[NS0];
__device__ int   g_deg_in0[ND0];
__device__ int   g_rowptr0[ND0 + 1];
__device__ int   g_fill0[ND0];
__device__ int   g_csr_src0[NE0];
__device__ float g_csr_w0[NE0];
__device__ float g_h1[(size_t)ND0 * HIDF];     // 25.6 MB

__device__ int   g_deg_out1[NS1];
__device__ int   g_deg_in1[ND1];
__device__ int   g_rowptr1[ND1 + 1];
__device__ int   g_fill1[ND1];
__device__ int   g_csr_src1[NE1];
__device__ float g_csr_w1[NE1];

// ---------------- helpers ----------------
__device__ __forceinline__ uint32_t f2tf32(float f) {
    uint32_t r;
    asm("cvt.rna.tf32.f32 %0, %1;" : "=r"(r) : "f"(f));
    return r;
}

__device__ __forceinline__ void mma_tf32(float d[4], const uint32_t a[4],
                                         const uint32_t b0, const uint32_t b1,
                                         const float c[4]) {
    asm volatile(
        "mma.sync.aligned.m16n8k8.row.col.f32.tf32.tf32.f32 "
        "{%0,%1,%2,%3}, {%4,%5,%6,%7}, {%8,%9}, {%10,%11,%12,%13};\n"
        : "=f"(d[0]), "=f"(d[1]), "=f"(d[2]), "=f"(d[3])
        : "r"(a[0]), "r"(a[1]), "r"(a[2]), "r"(a[3]),
          "r"(b0), "r"(b1),
          "f"(c[0]), "f"(c[1]), "f"(c[2]), "f"(c[3]));
}

// ---------------- preprocessing ----------------

__global__ void k_zero() {
    int i = blockIdx.x * blockDim.x + threadIdx.x;
    int stride = gridDim.x * blockDim.x;
    for (int j = i; j < NS0; j += stride) g_deg_out0[j] = 0;
    for (int j = i; j < ND0; j += stride) {
        g_deg_in0[j] = 0;
        g_fill0[j] = 0;
        g_deg_out1[j] = 0;   // NS1 == ND0
    }
    for (int j = i; j < ND1; j += stride) {
        g_deg_in1[j] = 0;
        g_fill1[j] = 0;
    }
}

// 4 edges per thread via int4 loads. NE0/4 = 200000 threads.
__global__ void __launch_bounds__(256) k_degree(const int* __restrict__ src0,
                                                const int* __restrict__ dst0,
                                                const int* __restrict__ src1,
                                                const int* __restrict__ dst1) {
    int i = blockIdx.x * blockDim.x + threadIdx.x;
    if (i < NE0 / 4) {
        int4 s = ((const int4*)src0)[i];
        int4 d = ((const int4*)dst0)[i];
        atomicAdd(&g_deg_out0[s.x], 1); atomicAdd(&g_deg_out0[s.y], 1);
        atomicAdd(&g_deg_out0[s.z], 1); atomicAdd(&g_deg_out0[s.w], 1);
        atomicAdd(&g_deg_in0[d.x], 1);  atomicAdd(&g_deg_in0[d.y], 1);
        atomicAdd(&g_deg_in0[d.z], 1);  atomicAdd(&g_deg_in0[d.w], 1);
    }
    if (i < NE1 / 4) {
        int4 s = ((const int4*)src1)[i];
        int4 d = ((const int4*)dst1)[i];
        atomicAdd(&g_deg_out1[s.x], 1); atomicAdd(&g_deg_out1[s.y], 1);
        atomicAdd(&g_deg_out1[s.z], 1); atomicAdd(&g_deg_out1[s.w], 1);
        atomicAdd(&g_deg_in1[d.x], 1);  atomicAdd(&g_deg_in1[d.y], 1);
        atomicAdd(&g_deg_in1[d.z], 1);  atomicAdd(&g_deg_in1[d.w], 1);
    }
}

__device__ __forceinline__ void scan_body(const int* __restrict__ deg,
                                          int* __restrict__ rowptr, int n) {
    __shared__ int partial[1024];
    const int t = threadIdx.x;
    const int C = (n + 1023) / 1024;
    const int start = t * C;
    const int end = min(start + C, n);
    int s = 0;
    for (int i = start; i < end; i++) s += deg[i];
    partial[t] = s;
    __syncthreads();
    for (int off = 1; off < 1024; off <<= 1) {
        int v = partial[t];
        int add = (t >= off) ? partial[t - off] : 0;
        __syncthreads();
        partial[t] = v + add;
        __syncthreads();
    }
    int run = (t == 0) ? 0 : partial[t - 1];
    for (int i = start; i < end; i++) {
        rowptr[i] = run;
        run += deg[i];
    }
    if (t == 0) rowptr[n] = partial[1023];
}

__global__ void k_scan_both() {
    if (blockIdx.x == 0) scan_body(g_deg_in0, g_rowptr0, ND0);
    else                 scan_body(g_deg_in1, g_rowptr1, ND1);
}

// 4 edges per thread.
__global__ void __launch_bounds__(256) k_fill(const int* __restrict__ src0,
                                              const int* __restrict__ dst0,
                                              const float* __restrict__ ew0,
                                              const int* __restrict__ src1,
                                              const int* __restrict__ dst1,
                                              const float* __restrict__ ew1) {
    int i = blockIdx.x * blockDim.x + threadIdx.x;
    if (i < NE0 / 4) {
        int4   s = ((const int4*)src0)[i];
        int4   d = ((const int4*)dst0)[i];
        float4 w = ((const float4*)ew0)[i];
        int ss[4] = {s.x, s.y, s.z, s.w};
        int dd[4] = {d.x, d.y, d.z, d.w};
        float ww[4] = {w.x, w.y, w.z, w.w};
#pragma unroll
        for (int u = 0; u < 4; u++) {
            int pos = g_rowptr0[dd[u]] + atomicAdd(&g_fill0[dd[u]], 1);
            g_csr_src0[pos] = ss[u];
            g_csr_w0[pos] = ww[u] * rsqrtf(fmaxf((float)g_deg_out0[ss[u]], 1.0f));
        }
    }
    if (i < NE1 / 4) {
        int4   s = ((const int4*)src1)[i];
        int4   d = ((const int4*)dst1)[i];
        float4 w = ((const float4*)ew1)[i];
        int ss[4] = {s.x, s.y, s.z, s.w};
        int dd[4] = {d.x, d.y, d.z, d.w};
        float ww[4] = {w.x, w.y, w.z, w.w};
#pragma unroll
        for (int u = 0; u < 4; u++) {
            int pos = g_rowptr1[dd[u]] + atomicAdd(&g_fill1[dd[u]], 1);
            g_csr_src1[pos] = ss[u];
            g_csr_w1[pos] = ww[u] * rsqrtf(fmaxf((float)g_deg_out1[ss[u]], 1.0f));
        }
    }
}

// ---------------- fused aggregate + TF32 GEMM ----------------
// Per block (256 threads): gather 64 dst rows (D feats each) into smem,
// then compute relu(A[64,D] @ W[D,128] + bias) with tensor cores.
// Smem: Ash float[64][D+4]  (+4 pad -> conflict-free mma fragment loads)
//       Wsh u32 [32][136]
template <int D>
__global__ void __launch_bounds__(256) k_fused(const int* __restrict__ rowptr,
                                               const int* __restrict__ csrsrc,
                                               const float* __restrict__ csrw,
                                               const float* __restrict__ feat,
                                               const int* __restrict__ indeg,
                                               const float* __restrict__ W,
                                               const float* __restrict__ bias,
                                               float* __restrict__ out,
                                               int nrows) {
    constexpr int ASTRIDE = D + 4;
    constexpr int TPR = D / 4;           // threads per row (float4 each)
    constexpr int ROWS_PAR = 256 / TPR;  // rows gathered in parallel
    extern __shared__ char smem_raw[];
    float*    Ash = (float*)smem_raw;                       // 64*ASTRIDE floats
    uint32_t* Wsh = (uint32_t*)(smem_raw + 64 * ASTRIDE * 4); // 32*136 u32

    const int tid = threadIdx.x;
    const int base = blockIdx.x * 64;

    // ---- Phase 1: gather ----
    {
        const int rgrp = tid / TPR;       // which of ROWS_PAR rows
        const int lanein = tid % TPR;
        const int c4 = lanein * 4;
        for (int rr = rgrp; rr < 64; rr += ROWS_PAR) {
            const int row = base + rr;
            float4 acc = make_float4(0.f, 0.f, 0.f, 0.f);
            if (row < nrows) {
                const int beg = __ldg(&rowptr[row]);
                const int end = __ldg(&rowptr[row + 1]);
                int j = beg;
                for (; j + 8 <= end; j += 8) {
                    int   s[8];
                    float w[8];
#pragma unroll
                    for (int u = 0; u < 8; u++) {
                        s[u] = __ldg(&csrsrc[j + u]);
                        w[u] = __ldg(&csrw[j + u]);
                    }
                    float4 f[8];
#pragma unroll
                    for (int u = 0; u < 8; u++)
                        f[u] = __ldg((const float4*)&feat[(size_t)s[u] * D + c4]);
#pragma unroll
                    for (int u = 0; u < 8; u++) {
                        acc.x += w[u] * f[u].x;
                        acc.y += w[u] * f[u].y;
                        acc.z += w[u] * f[u].z;
                        acc.w += w[u] * f[u].w;
                    }
                }
                for (; j < end; j++) {
                    float wv = __ldg(&csrw[j]);
                    float4 f = __ldg((const float4*)&feat[(size_t)csrsrc[j] * D + c4]);
                    acc.x += wv * f.x; acc.y += wv * f.y;
                    acc.z += wv * f.z; acc.w += wv * f.w;
                }
                float sc = rsqrtf(fmaxf((float)__ldg(&indeg[row]), 1.0f));
                acc.x *= sc; acc.y *= sc; acc.z *= sc; acc.w *= sc;
            }
            float* dst = &Ash[rr * ASTRIDE + c4];
            dst[0] = acc.x; dst[1] = acc.y; dst[2] = acc.z; dst[3] = acc.w;
        }
    }

    // ---- Phase 2: TF32 GEMM 64xD @ Dx128 ----
    const int lane = tid & 31;
    const int warp = tid >> 5;      // 0..7
    const int warpM = warp & 3;     // 4 along M: 16 rows each
    const int warpN = warp >> 2;    // 2 along N: 64 cols each

    float acc[8][4];
#pragma unroll
    for (int nt = 0; nt < 8; nt++)
#pragma unroll
        for (int i = 0; i < 4; i++) acc[nt][i] = 0.0f;

    for (int kc = 0; kc < D; kc += 32) {
        __syncthreads();
        // Load W tile 32x128 (convert to tf32)
#pragma unroll
        for (int it = 0; it < 4; it++) {
            int kk = (tid >> 5) + it * 8;
            int n = (tid & 31) * 4;
            float4 v = *(const float4*)&W[(size_t)(kc + kk) * 128 + n];
            uint32_t* dst = &Wsh[kk * 136 + n];
            dst[0] = f2tf32(v.x); dst[1] = f2tf32(v.y);
            dst[2] = f2tf32(v.z); dst[3] = f2tf32(v.w);
        }
        __syncthreads();

#pragma unroll
        for (int k8 = 0; k8 < 4; k8++) {
            const int kb = k8 * 8;
            const int rA = warpM * 16 + (lane >> 2);
            const int cA = kc + kb + (lane & 3);
            uint32_t afr[4];
            afr[0] = f2tf32(Ash[rA * ASTRIDE + cA]);
            afr[1] = f2tf32(Ash[(rA + 8) * ASTRIDE + cA]);
            afr[2] = f2tf32(Ash[rA * ASTRIDE + cA + 4]);
            afr[3] = f2tf32(Ash[(rA + 8) * ASTRIDE + cA + 4]);
            const int kkB = kb + (lane & 3);
#pragma unroll
            for (int nt = 0; nt < 8; nt++) {
                const int n = warpN * 64 + nt * 8 + (lane >> 2);
                uint32_t b0 = Wsh[kkB * 136 + n];
                uint32_t b1 = Wsh[(kkB + 4) * 136 + n];
                mma_tf32(acc[nt], afr, b0, b1, acc[nt]);
            }
        }
    }

    // ---- Epilogue: bias + relu ----
#pragma unroll
    for (int nt = 0; nt < 8; nt++) {
        int col = warpN * 64 + nt * 8 + (lane & 3) * 2;
        float bb0 = __ldg(&bias[col]);
        float bb1 = __ldg(&bias[col + 1]);
        int r0 = base + warpM * 16 + (lane >> 2);
        if (r0 < nrows) {
            float2 v;
            v.x = fmaxf(acc[nt][0] + bb0, 0.0f);
            v.y = fmaxf(acc[nt][1] + bb1, 0.0f);
            *(float2*)&out[(size_t)r0 * 128 + col] = v;
        }
        int r1 = r0 + 8;
        if (r1 < nrows) {
            float2 v;
            v.x = fmaxf(acc[nt][2] + bb0, 0.0f);
            v.y = fmaxf(acc[nt][3] + bb1, 0.0f);
            *(float2*)&out[(size_t)r1 * 128 + col] = v;
        }
    }
}

// ---------------- launch ----------------
extern "C" void kernel_launch(void* const* d_in, const int* in_sizes, int n_in,
                              void* d_out, int out_size) {
    const float* x    = (const float*)d_in[0];
    const int*   src0 = (const int*)d_in[1];
    const int*   dst0 = (const int*)d_in[2];
    const float* ew0  = (const float*)d_in[3];
    const int*   src1 = (const int*)d_in[4];
    const int*   dst1 = (const int*)d_in[5];
    const float* ew1  = (const float*)d_in[6];
    const float* W1   = (const float*)d_in[7];
    const float* b1   = (const float*)d_in[8];
    const float* W2   = (const float*)d_in[9];
    const float* b2   = (const float*)d_in[10];
    float* out = (float*)d_out;

    int *rowptr0, *csrsrc0, *indeg0, *rowptr1, *csrsrc1, *indeg1;
    float *csrw0, *csrw1, *h1;
    cudaGetSymbolAddress((void**)&rowptr0, g_rowptr0);
    cudaGetSymbolAddress((void**)&csrsrc0, g_csr_src0);
    cudaGetSymbolAddress((void**)&csrw0,   g_csr_w0);
    cudaGetSymbolAddress((void**)&indeg0,  g_deg_in0);
    cudaGetSymbolAddress((void**)&rowptr1, g_rowptr1);
    cudaGetSymbolAddress((void**)&csrsrc1, g_csr_src1);
    cudaGetSymbolAddress((void**)&csrw1,   g_csr_w1);
    cudaGetSymbolAddress((void**)&indeg1,  g_deg_in1);
    cudaGetSymbolAddress((void**)&h1,      g_h1);

    const int smem1 = (64 * (INF + 4)) * 4 + 32 * 136 * 4;   // 83968
    const int smem2 = (64 * (HIDF + 4)) * 4 + 32 * 136 * 4;  // 51200
    cudaFuncSetAttribute(k_fused<INF>,  cudaFuncAttributeMaxDynamicSharedMemorySize, smem1);
    cudaFuncSetAttribute(k_fused<HIDF>, cudaFuncAttributeMaxDynamicSharedMemorySize, smem2);

    k_zero<<<256, 256>>>();
    k_degree<<<(NE0 / 4 + 255) / 256, 256>>>(src0, dst0, src1, dst1);
    k_scan_both<<<2, 1024>>>();
    k_fill<<<(NE0 / 4 + 255) / 256, 256>>>(src0, dst0, ew0, src1, dst1, ew1);
    k_fused<INF><<<(ND0 + 63) / 64, 256, smem1>>>(rowptr0, csrsrc0, csrw0, x,
                                                  indeg0, W1, b1, h1, ND0);
    k_fused<HIDF><<<(ND1 + 63) / 64, 256, smem2>>>(rowptr1, csrsrc1, csrw1, h1,
                                                   indeg1, W2, b2, out, ND1);
}

// round 4
// speedup vs baseline: 1.6731x; 1.1831x over previous
#include <cuda_runtime.h>
#include <cuda_bf16.h>
#include <cstdint>

#define NS0 300000
#define ND0 50000
#define NE0 800000
#define NS1 50000
#define ND1 8192
#define NE1 131072
#define INF 256
#define HIDF 128
#define OUTF 128

// ---------------- static device scratch ----------------
__device__ int   g_deg_out0[NS0];
__device__ int   g_deg_in0[ND0];
__device__ int   g_rowptr0[ND0 + 1];
__device__ int   g_fill0[ND0];
__device__ int   g_csr_src0[NE0];
__device__ float g_csr_w0[NE0];
__device__ float g_h1[(size_t)ND0 * HIDF];     // 25.6 MB

__device__ int   g_deg_out1[NS1];
__device__ int   g_deg_in1[ND1];
__device__ int   g_rowptr1[ND1 + 1];
__device__ int   g_fill1[ND1];
__device__ int   g_csr_src1[NE1];
__device__ float g_csr_w1[NE1];

// ---------------- helpers ----------------
__device__ __forceinline__ uint32_t f2tf32(float f) {
    uint32_t r;
    asm("cvt.rna.tf32.f32 %0, %1;" : "=r"(r) : "f"(f));
    return r;
}

__device__ __forceinline__ void mma_tf32(float d[4], const uint32_t a[4],
                                         const uint32_t b0, const uint32_t b1,
                                         const float c[4]) {
    asm volatile(
        "mma.sync.aligned.m16n8k8.row.col.f32.tf32.tf32.f32 "
        "{%0,%1,%2,%3}, {%4,%5,%6,%7}, {%8,%9}, {%10,%11,%12,%13};\n"
        : "=f"(d[0]), "=f"(d[1]), "=f"(d[2]), "=f"(d[3])
        : "r"(a[0]), "r"(a[1]), "r"(a[2]), "r"(a[3]),
          "r"(b0), "r"(b1),
          "f"(c[0]), "f"(c[1]), "f"(c[2]), "f"(c[3]));
}

// ---------------- preprocessing ----------------

__global__ void k_zero() {
    int i = blockIdx.x * blockDim.x + threadIdx.x;
    int stride = gridDim.x * blockDim.x;
    for (int j = i; j < NS0; j += stride) g_deg_out0[j] = 0;
    for (int j = i; j < ND0; j += stride) {
        g_deg_in0[j] = 0;
        g_fill0[j] = 0;
        g_deg_out1[j] = 0;   // NS1 == ND0
    }
    for (int j = i; j < ND1; j += stride) {
        g_deg_in1[j] = 0;
        g_fill1[j] = 0;
    }
}

// 2 edges per thread via int2 loads -> 400k threads (full occupancy).
__global__ void __launch_bounds__(256) k_degree(const int* __restrict__ src0,
                                                const int* __restrict__ dst0,
                                                const int* __restrict__ src1,
                                                const int* __restrict__ dst1) {
    int i = blockIdx.x * blockDim.x + threadIdx.x;
    if (i < NE0 / 2) {
        int2 s = ((const int2*)src0)[i];
        int2 d = ((const int2*)dst0)[i];
        atomicAdd(&g_deg_out0[s.x], 1); atomicAdd(&g_deg_out0[s.y], 1);
        atomicAdd(&g_deg_in0[d.x], 1);  atomicAdd(&g_deg_in0[d.y], 1);
    }
    if (i < NE1 / 2) {
        int2 s = ((const int2*)src1)[i];
        int2 d = ((const int2*)dst1)[i];
        atomicAdd(&g_deg_out1[s.x], 1); atomicAdd(&g_deg_out1[s.y], 1);
        atomicAdd(&g_deg_in1[d.x], 1);  atomicAdd(&g_deg_in1[d.y], 1);
    }
}

__device__ __forceinline__ void scan_body(const int* __restrict__ deg,
                                          int* __restrict__ rowptr, int n) {
    __shared__ int partial[1024];
    const int t = threadIdx.x;
    const int C = (n + 1023) / 1024;
    const int start = t * C;
    const int end = min(start + C, n);
    int s = 0;
    for (int i = start; i < end; i++) s += deg[i];
    partial[t] = s;
    __syncthreads();
    for (int off = 1; off < 1024; off <<= 1) {
        int v = partial[t];
        int add = (t >= off) ? partial[t - off] : 0;
        __syncthreads();
        partial[t] = v + add;
        __syncthreads();
    }
    int run = (t == 0) ? 0 : partial[t - 1];
    for (int i = start; i < end; i++) {
        rowptr[i] = run;
        run += deg[i];
    }
    if (t == 0) rowptr[n] = partial[1023];
}

__global__ void k_scan_both() {
    if (blockIdx.x == 0) scan_body(g_deg_in0, g_rowptr0, ND0);
    else                 scan_body(g_deg_in1, g_rowptr1, ND1);
}

// 2 edges per thread.
__global__ void __launch_bounds__(256) k_fill(const int* __restrict__ src0,
                                              const int* __restrict__ dst0,
                                              const float* __restrict__ ew0,
                                              const int* __restrict__ src1,
                                              const int* __restrict__ dst1,
                                              const float* __restrict__ ew1) {
    int i = blockIdx.x * blockDim.x + threadIdx.x;
    if (i < NE0 / 2) {
        int2   s = ((const int2*)src0)[i];
        int2   d = ((const int2*)dst0)[i];
        float2 w = ((const float2*)ew0)[i];
        int pos0 = g_rowptr0[d.x] + atomicAdd(&g_fill0[d.x], 1);
        int pos1 = g_rowptr0[d.y] + atomicAdd(&g_fill0[d.y], 1);
        g_csr_src0[pos0] = s.x;
        g_csr_src0[pos1] = s.y;
        g_csr_w0[pos0] = w.x * rsqrtf(fmaxf((float)g_deg_out0[s.x], 1.0f));
        g_csr_w0[pos1] = w.y * rsqrtf(fmaxf((float)g_deg_out0[s.y], 1.0f));
    }
    if (i < NE1 / 2) {
        int2   s = ((const int2*)src1)[i];
        int2   d = ((const int2*)dst1)[i];
        float2 w = ((const float2*)ew1)[i];
        int pos0 = g_rowptr1[d.x] + atomicAdd(&g_fill1[d.x], 1);
        int pos1 = g_rowptr1[d.y] + atomicAdd(&g_fill1[d.y], 1);
        g_csr_src1[pos0] = s.x;
        g_csr_src1[pos1] = s.y;
        g_csr_w1[pos0] = w.x * rsqrtf(fmaxf((float)g_deg_out1[s.x], 1.0f));
        g_csr_w1[pos1] = w.y * rsqrtf(fmaxf((float)g_deg_out1[s.y], 1.0f));
    }
}

// ---------------- fused aggregate + TF32 GEMM ----------------
// Per block (512 threads): gather 64 dst rows (D feats each) into smem,
// then compute relu(A[64,D] @ W[D,128] + bias) with tensor cores.
// 16 warps: 4 along M (16 rows each) x 4 along N (32 cols each).
template <int D>
__global__ void __launch_bounds__(512) k_fused(const int* __restrict__ rowptr,
                                               const int* __restrict__ csrsrc,
                                               const float* __restrict__ csrw,
                                               const float* __restrict__ feat,
                                               const int* __restrict__ indeg,
                                               const float* __restrict__ W,
                                               const float* __restrict__ bias,
                                               float* __restrict__ out,
                                               int nrows) {
    constexpr int ASTRIDE = D + 4;
    constexpr int TPR = D / 4;           // threads per row (float4 each)
    constexpr int ROWS_PAR = 512 / TPR;  // rows gathered in parallel
    extern __shared__ char smem_raw[];
    float*    Ash = (float*)smem_raw;                          // 64*ASTRIDE floats
    uint32_t* Wsh = (uint32_t*)(smem_raw + 64 * ASTRIDE * 4);  // 32*136 u32

    const int tid = threadIdx.x;
    const int base = blockIdx.x * 64;

    // ---- Phase 1: gather ----
    {
        const int rgrp = tid / TPR;
        const int lanein = tid % TPR;
        const int c4 = lanein * 4;
#pragma unroll
        for (int rr = rgrp; rr < 64; rr += ROWS_PAR) {
            const int row = base + rr;
            float4 acc = make_float4(0.f, 0.f, 0.f, 0.f);
            if (row < nrows) {
                const int beg = __ldg(&rowptr[row]);
                const int end = __ldg(&rowptr[row + 1]);
                int j = beg;
                for (; j + 8 <= end; j += 8) {
                    int   s[8];
                    float w[8];
#pragma unroll
                    for (int u = 0; u < 8; u++) {
                        s[u] = __ldg(&csrsrc[j + u]);
                        w[u] = __ldg(&csrw[j + u]);
                    }
                    float4 f[8];
#pragma unroll
                    for (int u = 0; u < 8; u++)
                        f[u] = __ldg((const float4*)&feat[(size_t)s[u] * D + c4]);
#pragma unroll
                    for (int u = 0; u < 8; u++) {
                        acc.x += w[u] * f[u].x;
                        acc.y += w[u] * f[u].y;
                        acc.z += w[u] * f[u].z;
                        acc.w += w[u] * f[u].w;
                    }
                }
                for (; j < end; j++) {
                    float wv = __ldg(&csrw[j]);
                    float4 f = __ldg((const float4*)&feat[(size_t)csrsrc[j] * D + c4]);
                    acc.x += wv * f.x; acc.y += wv * f.y;
                    acc.z += wv * f.z; acc.w += wv * f.w;
                }
                float sc = rsqrtf(fmaxf((float)__ldg(&indeg[row]), 1.0f));
                acc.x *= sc; acc.y *= sc; acc.z *= sc; acc.w *= sc;
            }
            float* dst = &Ash[rr * ASTRIDE + c4];
            dst[0] = acc.x; dst[1] = acc.y; dst[2] = acc.z; dst[3] = acc.w;
        }
    }

    // ---- Phase 2: TF32 GEMM 64xD @ Dx128 ----
    const int lane = tid & 31;
    const int warp = tid >> 5;      // 0..15
    const int warpM = warp & 3;     // 4 along M: 16 rows each
    const int warpN = warp >> 2;    // 4 along N: 32 cols each

    float acc[4][4];
#pragma unroll
    for (int nt = 0; nt < 4; nt++)
#pragma unroll
        for (int i = 0; i < 4; i++) acc[nt][i] = 0.0f;

    for (int kc = 0; kc < D; kc += 32) {
        __syncthreads();
        // Load W tile 32x128 (convert to tf32); 512 threads x 2 float4 each
#pragma unroll
        for (int it = 0; it < 2; it++) {
            int kk = (tid >> 5) + it * 16;
            int n = (tid & 31) * 4;
            float4 v = *(const float4*)&W[(size_t)(kc + kk) * 128 + n];
            uint32_t* dst = &Wsh[kk * 136 + n];
            dst[0] = f2tf32(v.x); dst[1] = f2tf32(v.y);
            dst[2] = f2tf32(v.z); dst[3] = f2tf32(v.w);
        }
        __syncthreads();

#pragma unroll
        for (int k8 = 0; k8 < 4; k8++) {
            const int kb = k8 * 8;
            const int rA = warpM * 16 + (lane >> 2);
            const int cA = kc + kb + (lane & 3);
            uint32_t afr[4];
            afr[0] = f2tf32(Ash[rA * ASTRIDE + cA]);
            afr[1] = f2tf32(Ash[(rA + 8) * ASTRIDE + cA]);
            afr[2] = f2tf32(Ash[rA * ASTRIDE + cA + 4]);
            afr[3] = f2tf32(Ash[(rA + 8) * ASTRIDE + cA + 4]);
            const int kkB = kb + (lane & 3);
#pragma unroll
            for (int nt = 0; nt < 4; nt++) {
                const int n = warpN * 32 + nt * 8 + (lane >> 2);
                uint32_t b0 = Wsh[kkB * 136 + n];
                uint32_t b1 = Wsh[(kkB + 4) * 136 + n];
                mma_tf32(acc[nt], afr, b0, b1, acc[nt]);
            }
        }
    }

    // ---- Epilogue: bias + relu ----
#pragma unroll
    for (int nt = 0; nt < 4; nt++) {
        int col = warpN * 32 + nt * 8 + (lane & 3) * 2;
        float bb0 = __ldg(&bias[col]);
        float bb1 = __ldg(&bias[col + 1]);
        int r0 = base + warpM * 16 + (lane >> 2);
        if (r0 < nrows) {
            float2 v;
            v.x = fmaxf(acc[nt][0] + bb0, 0.0f);
            v.y = fmaxf(acc[nt][1] + bb1, 0.0f);
            *(float2*)&out[(size_t)r0 * 128 + col] = v;
        }
        int r1 = r0 + 8;
        if (r1 < nrows) {
            float2 v;
            v.x = fmaxf(acc[nt][2] + bb0, 0.0f);
            v.y = fmaxf(acc[nt][3] + bb1, 0.0f);
            *(float2*)&out[(size_t)r1 * 128 + col] = v;
        }
    }
}

// ---------------- launch ----------------
extern "C" void kernel_launch(void* const* d_in, const int* in_sizes, int n_in,
                              void* d_out, int out_size) {
    const float* x    = (const float*)d_in[0];
    const int*   src0 = (const int*)d_in[1];
    const int*   dst0 = (const int*)d_in[2];
    const float* ew0  = (const float*)d_in[3];
    const int*   src1 = (const int*)d_in[4];
    const int*   dst1 = (const int*)d_in[5];
    const float* ew1  = (const float*)d_in[6];
    const float* W1   = (const float*)d_in[7];
    const float* b1   = (const float*)d_in[8];
    const float* W2   = (const float*)d_in[9];
    const float* b2   = (const float*)d_in[10];
    float* out = (float*)d_out;

    int *rowptr0, *csrsrc0, *indeg0, *rowptr1, *csrsrc1, *indeg1;
    float *csrw0, *csrw1, *h1;
    cudaGetSymbolAddress((void**)&rowptr0, g_rowptr0);
    cudaGetSymbolAddress((void**)&csrsrc0, g_csr_src0);
    cudaGetSymbolAddress((void**)&csrw0,   g_csr_w0);
    cudaGetSymbolAddress((void**)&indeg0,  g_deg_in0);
    cudaGetSymbolAddress((void**)&rowptr1, g_rowptr1);
    cudaGetSymbolAddress((void**)&csrsrc1, g_csr_src1);
    cudaGetSymbolAddress((void**)&csrw1,   g_csr_w1);
    cudaGetSymbolAddress((void**)&indeg1,  g_deg_in1);
    cudaGetSymbolAddress((void**)&h1,      g_h1);

    const int smem1 = (64 * (INF + 4)) * 4 + 32 * 136 * 4;   // 83968
    const int smem2 = (64 * (HIDF + 4)) * 4 + 32 * 136 * 4;  // 51200
    cudaFuncSetAttribute(k_fused<INF>,  cudaFuncAttributeMaxDynamicSharedMemorySize, smem1);
    cudaFuncSetAttribute(k_fused<HIDF>, cudaFuncAttributeMaxDynamicSharedMemorySize, smem2);

    k_zero<<<256, 256>>>();
    k_degree<<<(NE0 / 2 + 255) / 256, 256>>>(src0, dst0, src1, dst1);
    k_scan_both<<<2, 1024>>>();
    k_fill<<<(NE0 / 2 + 255) / 256, 256>>>(src0, dst0, ew0, src1, dst1, ew1);
    k_fused<INF><<<(ND0 + 63) / 64, 512, smem1>>>(rowptr0, csrsrc0, csrw0, x,
                                                  indeg0, W1, b1, h1, ND0);
    k_fused<HIDF><<<(ND1 + 63) / 64, 512, smem2>>>(rowptr1, csrsrc1, csrw1, h1,
                                                   indeg1, W2, b2, out, ND1);
}